// round 7
// baseline (speedup 1.0000x reference)
#include <cuda_runtime.h>

// Problem constants
#define PB 2
#define PS 2048
#define PD 1024
#define PH 16
#define PDH 64
#define PBS (PB * PS)                        // 4096 rows
#define OUT_ELEMS ((long long)PB * PS * PD)  // 4194304

// Scratch (device globals; no allocation allowed)
__device__ float g_Q[(size_t)PB * PH * PS * PDH];   // [b][h][s][k]
__device__ float g_K[(size_t)PB * PH * PS * PDH];
__device__ float g_V[(size_t)PB * PH * PS * PDH];
__device__ float g_ctx[(size_t)PB * PS * PD];       // [b][s][h*64+k]

// ---------------------------------------------------------------------------
// Kernel 1: fused Q/K/V per-head projections.
// C[128 x 128] = A[128 x 1024] * W[1024 x 128] (+bias, Q scaled by 1/8)
// blockIdx.x: M tile (128 rows of B*S), blockIdx.y: 2 heads, blockIdx.z: q/k/v
// ---------------------------------------------------------------------------
__global__ __launch_bounds__(256) void qkv_proj_kernel(
    const float* __restrict__ q, const float* __restrict__ k,
    const float* __restrict__ v, const float* __restrict__ Wq,
    const float* __restrict__ Wk, const float* __restrict__ Wv,
    const float* __restrict__ bq, const float* __restrict__ bk,
    const float* __restrict__ bv)
{
    __shared__ float As[16][132];   // transposed: As[kk][m]
    __shared__ float Bs[16][128];   // Bs[kk][j]

    const int zz = blockIdx.z;
    const float* A    = (zz == 0) ? q  : (zz == 1) ? k  : v;
    const float* W    = (zz == 0) ? Wq : (zz == 1) ? Wk : Wv;
    const float* bias = (zz == 0) ? bq : (zz == 1) ? bk : bv;
    float* outp       = (zz == 0) ? g_Q : (zz == 1) ? g_K : g_V;
    const float scale = (zz == 0) ? 0.125f : 1.0f;   // 1/sqrt(DH) folded into Q

    const int m0 = blockIdx.x * 128;
    const int h0 = blockIdx.y * 2;          // two heads per N-tile of 128
    const int tid = threadIdx.x;
    const int tx = tid & 15;
    const int ty = tid >> 4;

    float acc[8][8];
#pragma unroll
    for (int i = 0; i < 8; i++)
#pragma unroll
        for (int j = 0; j < 8; j++) acc[i][j] = 0.f;

    for (int d0 = 0; d0 < PD; d0 += 16) {
        // A tile 128x16, transposed into smem
#pragma unroll
        for (int l = 0; l < 2; l++) {
            int f = tid + 256 * l;
            int m = f >> 2, c4 = (f & 3) * 4;
            float4 av = *(const float4*)(A + (size_t)(m0 + m) * PD + d0 + c4);
            As[c4 + 0][m] = av.x; As[c4 + 1][m] = av.y;
            As[c4 + 2][m] = av.z; As[c4 + 3][m] = av.w;
        }
        // W tile 16x128 (two heads, each contiguous 64-wide)
#pragma unroll
        for (int l = 0; l < 2; l++) {
            int f = tid + 256 * l;
            int kk = f >> 5, c4 = (f & 31) * 4;
            int hh = h0 + (c4 >> 6);
            int kc = c4 & 63;
            *(float4*)&Bs[kk][c4] =
                *(const float4*)(W + ((size_t)hh * PD + (d0 + kk)) * PDH + kc);
        }
        __syncthreads();
#pragma unroll
        for (int kk = 0; kk < 16; kk++) {
            float a[8], bb[8];
            *(float4*)&a[0]  = *(const float4*)&As[kk][ty * 8];
            *(float4*)&a[4]  = *(const float4*)&As[kk][ty * 8 + 4];
            *(float4*)&bb[0] = *(const float4*)&Bs[kk][tx * 8];
            *(float4*)&bb[4] = *(const float4*)&Bs[kk][tx * 8 + 4];
#pragma unroll
            for (int i = 0; i < 8; i++)
#pragma unroll
                for (int j = 0; j < 8; j++) acc[i][j] += a[i] * bb[j];
        }
        __syncthreads();
    }

    // epilogue: bias + scale, store to [b][h][s][k] layout
    const int jbase = tx * 8;              // 8 cols, never straddles a head
    const int hh = h0 + (jbase >> 6);
    const int kc0 = jbase & 63;
    float bcol[8];
#pragma unroll
    for (int j = 0; j < 8; j++) bcol[j] = bias[hh * PDH + kc0 + j];

#pragma unroll
    for (int i = 0; i < 8; i++) {
        int r = m0 + ty * 8 + i;
        int bb_ = r >> 11;                 // / S
        int s = r & (PS - 1);
        float* dst = outp + ((size_t)(bb_ * PH + hh) * PS + s) * PDH + kc0;
        float o[8];
#pragma unroll
        for (int j = 0; j < 8; j++) o[j] = (acc[i][j] + bcol[j]) * scale;
        *(float4*)dst       = *(float4*)&o[0];
        *(float4*)(dst + 4) = *(float4*)&o[4];
    }
}

// ---------------------------------------------------------------------------
// Kernel 2: raw scores = Qh * Kh^T, written directly into aws[h][b][:, :]
// Per (b,h): M=N=2048, K=64. 128x128 tiles, 8x8 per thread.
// ---------------------------------------------------------------------------
__global__ __launch_bounds__(256) void scores_kernel(float* __restrict__ aw)
{
    __shared__ float As[16][132];
    __shared__ float Bs[16][132];

    const int zz = blockIdx.z;           // b*H + h
    const int b_ = zz >> 4, h_ = zz & 15;
    const float* Qh = g_Q + (size_t)zz * PS * PDH;
    const float* Kh = g_K + (size_t)zz * PS * PDH;
    float* awb = aw + (size_t)(h_ * PB + b_) * PS * PS;

    const int m0 = blockIdx.x * 128;     // query tile
    const int n0 = blockIdx.y * 128;     // key tile
    const int tid = threadIdx.x;
    const int tx = tid & 15, ty = tid >> 4;

    float acc[8][8];
#pragma unroll
    for (int i = 0; i < 8; i++)
#pragma unroll
        for (int j = 0; j < 8; j++) acc[i][j] = 0.f;

    for (int d0 = 0; d0 < PDH; d0 += 16) {
#pragma unroll
        for (int l = 0; l < 2; l++) {
            int f = tid + 256 * l;
            int m = f >> 2, c4 = (f & 3) * 4;
            float4 av = *(const float4*)(Qh + (size_t)(m0 + m) * PDH + d0 + c4);
            As[c4 + 0][m] = av.x; As[c4 + 1][m] = av.y;
            As[c4 + 2][m] = av.z; As[c4 + 3][m] = av.w;
            float4 kv = *(const float4*)(Kh + (size_t)(n0 + m) * PDH + d0 + c4);
            Bs[c4 + 0][m] = kv.x; Bs[c4 + 1][m] = kv.y;
            Bs[c4 + 2][m] = kv.z; Bs[c4 + 3][m] = kv.w;
        }
        __syncthreads();
#pragma unroll
        for (int kk = 0; kk < 16; kk++) {
            float a[8], bb[8];
            *(float4*)&a[0]  = *(const float4*)&As[kk][ty * 8];
            *(float4*)&a[4]  = *(const float4*)&As[kk][ty * 8 + 4];
            *(float4*)&bb[0] = *(const float4*)&Bs[kk][tx * 8];
            *(float4*)&bb[4] = *(const float4*)&Bs[kk][tx * 8 + 4];
#pragma unroll
            for (int i = 0; i < 8; i++)
#pragma unroll
                for (int j = 0; j < 8; j++) acc[i][j] += a[i] * bb[j];
        }
        __syncthreads();
    }

#pragma unroll
    for (int i = 0; i < 8; i++) {
        int qi = m0 + ty * 8 + i;
        float* dst = awb + (size_t)qi * PS + n0 + tx * 8;
        *(float4*)dst       = *(float4*)&acc[i][0];
        *(float4*)(dst + 4) = *(float4*)&acc[i][4];
    }
}

// ---------------------------------------------------------------------------
// Kernel 3: in-place row softmax over aws. One block per 2048-wide row,
// 8 elements per thread held in registers; two warp/block reductions.
// ---------------------------------------------------------------------------
__global__ __launch_bounds__(256) void softmax_kernel(float* __restrict__ aw)
{
    float* p = aw + (size_t)blockIdx.x * PS;
    const int t = threadIdx.x;
    const int lane = t & 31, warp = t >> 5;

    float x[8];
    *(float4*)&x[0] = ((const float4*)p)[t];
    *(float4*)&x[4] = ((const float4*)p)[t + 256];

    float m = x[0];
#pragma unroll
    for (int i = 1; i < 8; i++) m = fmaxf(m, x[i]);
#pragma unroll
    for (int o = 16; o > 0; o >>= 1) m = fmaxf(m, __shfl_xor_sync(0xffffffffu, m, o));

    __shared__ float red[8];
    if (lane == 0) red[warp] = m;
    __syncthreads();
    float mm = red[0];
#pragma unroll
    for (int i = 1; i < 8; i++) mm = fmaxf(mm, red[i]);

    float ssum = 0.f;
#pragma unroll
    for (int i = 0; i < 8; i++) { x[i] = __expf(x[i] - mm); ssum += x[i]; }
#pragma unroll
    for (int o = 16; o > 0; o >>= 1) ssum += __shfl_xor_sync(0xffffffffu, ssum, o);

    __syncthreads();                 // red[] reuse
    if (lane == 0) red[warp] = ssum;
    __syncthreads();
    float tot = 0.f;
#pragma unroll
    for (int i = 0; i < 8; i++) tot += red[i];
    float inv = 1.0f / tot;
#pragma unroll
    for (int i = 0; i < 8; i++) x[i] *= inv;

    ((float4*)p)[t]       = *(float4*)&x[0];
    ((float4*)p)[t + 256] = *(float4*)&x[4];
}

// ---------------------------------------------------------------------------
// Kernel 4: ctx = aw * V per (b,h): M=2048, N=64, K=2048. 128x64 tiles,
// 8x4 per thread. Output goes to head-concatenated [b][s][h*64+k].
// ---------------------------------------------------------------------------
__global__ __launch_bounds__(256) void ctx_kernel(const float* __restrict__ aw)
{
    __shared__ float As[16][132];   // transposed aw tile
    __shared__ float Bs[16][64];    // V tile, natural layout

    const int zz = blockIdx.z;
    const int b_ = zz >> 4, h_ = zz & 15;
    const float* awb = aw + (size_t)(h_ * PB + b_) * PS * PS;
    const float* Vh = g_V + (size_t)zz * PS * PDH;

    const int m0 = blockIdx.x * 128;
    const int tid = threadIdx.x;
    const int tx = tid & 15, ty = tid >> 4;

    float acc[8][4];
#pragma unroll
    for (int i = 0; i < 8; i++)
#pragma unroll
        for (int j = 0; j < 4; j++) acc[i][j] = 0.f;

    for (int kc = 0; kc < PS; kc += 16) {
#pragma unroll
        for (int l = 0; l < 2; l++) {
            int f = tid + 256 * l;
            int m = f >> 2, c4 = (f & 3) * 4;
            float4 av = *(const float4*)(awb + (size_t)(m0 + m) * PS + kc + c4);
            As[c4 + 0][m] = av.x; As[c4 + 1][m] = av.y;
            As[c4 + 2][m] = av.z; As[c4 + 3][m] = av.w;
        }
        {
            int kk = tid >> 4, c4 = (tid & 15) * 4;
            *(float4*)&Bs[kk][c4] =
                *(const float4*)(Vh + (size_t)(kc + kk) * PDH + c4);
        }
        __syncthreads();
#pragma unroll
        for (int kk = 0; kk < 16; kk++) {
            float a[8];
            *(float4*)&a[0] = *(const float4*)&As[kk][ty * 8];
            *(float4*)&a[4] = *(const float4*)&As[kk][ty * 8 + 4];
            float4 b4 = *(const float4*)&Bs[kk][tx * 4];
            float bb[4] = {b4.x, b4.y, b4.z, b4.w};
#pragma unroll
            for (int i = 0; i < 8; i++)
#pragma unroll
                for (int j = 0; j < 4; j++) acc[i][j] += a[i] * bb[j];
        }
        __syncthreads();
    }

#pragma unroll
    for (int i = 0; i < 8; i++) {
        int s = m0 + ty * 8 + i;
        *(float4*)(g_ctx + (size_t)(b_ * PS + s) * PD + h_ * PDH + tx * 4) =
            *(float4*)&acc[i][0];
    }
}

// ---------------------------------------------------------------------------
// Kernel 5: out = ctx @ Wo + bo. M=4096, N=1024, K=1024. 128x128 tiles.
// ---------------------------------------------------------------------------
__global__ __launch_bounds__(256) void out_proj_kernel(
    const float* __restrict__ Wo, const float* __restrict__ bo,
    float* __restrict__ out)
{
    __shared__ float As[16][132];
    __shared__ float Bs[16][128];

    const int m0 = blockIdx.x * 128;
    const int n0 = blockIdx.y * 128;
    const int tid = threadIdx.x;
    const int tx = tid & 15, ty = tid >> 4;

    float acc[8][8];
#pragma unroll
    for (int i = 0; i < 8; i++)
#pragma unroll
        for (int j = 0; j < 8; j++) acc[i][j] = 0.f;

    for (int d0 = 0; d0 < PD; d0 += 16) {
#pragma unroll
        for (int l = 0; l < 2; l++) {
            int f = tid + 256 * l;
            int m = f >> 2, c4 = (f & 3) * 4;
            float4 av = *(const float4*)(g_ctx + (size_t)(m0 + m) * PD + d0 + c4);
            As[c4 + 0][m] = av.x; As[c4 + 1][m] = av.y;
            As[c4 + 2][m] = av.z; As[c4 + 3][m] = av.w;
        }
#pragma unroll
        for (int l = 0; l < 2; l++) {
            int f = tid + 256 * l;
            int kk = f >> 5, c4 = (f & 31) * 4;
            *(float4*)&Bs[kk][c4] =
                *(const float4*)(Wo + (size_t)(d0 + kk) * PD + n0 + c4);
        }
        __syncthreads();
#pragma unroll
        for (int kk = 0; kk < 16; kk++) {
            float a[8], bb[8];
            *(float4*)&a[0]  = *(const float4*)&As[kk][ty * 8];
            *(float4*)&a[4]  = *(const float4*)&As[kk][ty * 8 + 4];
            *(float4*)&bb[0] = *(const float4*)&Bs[kk][tx * 8];
            *(float4*)&bb[4] = *(const float4*)&Bs[kk][tx * 8 + 4];
#pragma unroll
            for (int i = 0; i < 8; i++)
#pragma unroll
                for (int j = 0; j < 8; j++) acc[i][j] += a[i] * bb[j];
        }
        __syncthreads();
    }

    float bcol[8];
#pragma unroll
    for (int j = 0; j < 8; j++) bcol[j] = bo[n0 + tx * 8 + j];

#pragma unroll
    for (int i = 0; i < 8; i++) {
        int r = m0 + ty * 8 + i;
        float* dst = out + (size_t)r * PD + n0 + tx * 8;
        float o[8];
#pragma unroll
        for (int j = 0; j < 8; j++) o[j] = acc[i][j] + bcol[j];
        *(float4*)dst       = *(float4*)&o[0];
        *(float4*)(dst + 4) = *(float4*)&o[4];
    }
}

// ---------------------------------------------------------------------------
extern "C" void kernel_launch(void* const* d_in, const int* in_sizes, int n_in,
                              void* d_out, int out_size)
{
    (void)in_sizes; (void)n_in; (void)out_size;
    const float* q  = (const float*)d_in[0];
    const float* k  = (const float*)d_in[1];
    const float* v  = (const float*)d_in[2];
    const float* Wq = (const float*)d_in[3];
    const float* Wk = (const float*)d_in[4];
    const float* Wv = (const float*)d_in[5];
    const float* bq = (const float*)d_in[6];
    const float* bk = (const float*)d_in[7];
    const float* bv = (const float*)d_in[8];
    const float* Wo = (const float*)d_in[9];
    const float* bo = (const float*)d_in[10];

    float* out = (float*)d_out;
    float* aw  = out + OUT_ELEMS;    // aws [H][B][S][S] follows out [B][S][D]

    qkv_proj_kernel<<<dim3(PBS / 128, PD / 128, 3), 256>>>(
        q, k, v, Wq, Wk, Wv, bq, bk, bv);
    scores_kernel<<<dim3(PS / 128, PS / 128, PB * PH), 256>>>(aw);
    softmax_kernel<<<PB * PH * PS, 256>>>(aw);
    ctx_kernel<<<dim3(PS / 128, 1, PB * PH), 256>>>(aw);
    out_proj_kernel<<<dim3(PBS / 128, PD / 128), 256>>>(Wo, bo, out);
}

// round 8
// speedup vs baseline: 1.0010x; 1.0010x over previous
#include <cuda_runtime.h>

// Problem constants
#define PB 2
#define PS 2048
#define PD 1024
#define PH 16
#define PDH 64
#define PBS (PB * PS)                        // 4096 rows
#define OUT_ELEMS ((long long)PB * PS * PD)  // 4194304

// Scratch (device globals; no allocation allowed)
__device__ float g_Q[(size_t)PB * PH * PS * PDH];   // [b][h][s][k]
__device__ float g_K[(size_t)PB * PH * PS * PDH];
__device__ float g_V[(size_t)PB * PH * PS * PDH];
__device__ float g_ctx[(size_t)PB * PS * PD];       // [b][s][h*64+k]

// ---------------------------------------------------------------------------
// Kernel 1: fused Q/K/V per-head projections.
// C[128 x 128] = A[128 x 1024] * W[1024 x 128] (+bias, Q scaled by 1/8)
// blockIdx.x: M tile (128 rows of B*S), blockIdx.y: 2 heads, blockIdx.z: q/k/v
// ---------------------------------------------------------------------------
__global__ __launch_bounds__(256) void qkv_proj_kernel(
    const float* __restrict__ q, const float* __restrict__ k,
    const float* __restrict__ v, const float* __restrict__ Wq,
    const float* __restrict__ Wk, const float* __restrict__ Wv,
    const float* __restrict__ bq, const float* __restrict__ bk,
    const float* __restrict__ bv)
{
    __shared__ float As[16][132];   // transposed: As[kk][m]
    __shared__ float Bs[16][128];   // Bs[kk][j]

    const int zz = blockIdx.z;
    const float* A    = (zz == 0) ? q  : (zz == 1) ? k  : v;
    const float* W    = (zz == 0) ? Wq : (zz == 1) ? Wk : Wv;
    const float* bias = (zz == 0) ? bq : (zz == 1) ? bk : bv;
    float* outp       = (zz == 0) ? g_Q : (zz == 1) ? g_K : g_V;
    const float scale = (zz == 0) ? 0.125f : 1.0f;   // 1/sqrt(DH) folded into Q

    const int m0 = blockIdx.x * 128;
    const int h0 = blockIdx.y * 2;          // two heads per N-tile of 128
    const int tid = threadIdx.x;
    const int tx = tid & 15;
    const int ty = tid >> 4;

    float acc[8][8];
#pragma unroll
    for (int i = 0; i < 8; i++)
#pragma unroll
        for (int j = 0; j < 8; j++) acc[i][j] = 0.f;

    for (int d0 = 0; d0 < PD; d0 += 16) {
        // A tile 128x16, transposed into smem
#pragma unroll
        for (int l = 0; l < 2; l++) {
            int f = tid + 256 * l;
            int m = f >> 2, c4 = (f & 3) * 4;
            float4 av = *(const float4*)(A + (size_t)(m0 + m) * PD + d0 + c4);
            As[c4 + 0][m] = av.x; As[c4 + 1][m] = av.y;
            As[c4 + 2][m] = av.z; As[c4 + 3][m] = av.w;
        }
        // W tile 16x128 (two heads, each contiguous 64-wide)
#pragma unroll
        for (int l = 0; l < 2; l++) {
            int f = tid + 256 * l;
            int kk = f >> 5, c4 = (f & 31) * 4;
            int hh = h0 + (c4 >> 6);
            int kc = c4 & 63;
            *(float4*)&Bs[kk][c4] =
                *(const float4*)(W + ((size_t)hh * PD + (d0 + kk)) * PDH + kc);
        }
        __syncthreads();
#pragma unroll
        for (int kk = 0; kk < 16; kk++) {
            float a[8], bb[8];
            *(float4*)&a[0]  = *(const float4*)&As[kk][ty * 8];
            *(float4*)&a[4]  = *(const float4*)&As[kk][ty * 8 + 4];
            *(float4*)&bb[0] = *(const float4*)&Bs[kk][tx * 8];
            *(float4*)&bb[4] = *(const float4*)&Bs[kk][tx * 8 + 4];
#pragma unroll
            for (int i = 0; i < 8; i++)
#pragma unroll
                for (int j = 0; j < 8; j++) acc[i][j] += a[i] * bb[j];
        }
        __syncthreads();
    }

    // epilogue: bias + scale, store to [b][h][s][k] layout
    const int jbase = tx * 8;              // 8 cols, never straddles a head
    const int hh = h0 + (jbase >> 6);
    const int kc0 = jbase & 63;
    float bcol[8];
#pragma unroll
    for (int j = 0; j < 8; j++) bcol[j] = bias[hh * PDH + kc0 + j];

#pragma unroll
    for (int i = 0; i < 8; i++) {
        int r = m0 + ty * 8 + i;
        int bb_ = r >> 11;                 // / S
        int s = r & (PS - 1);
        float* dst = outp + ((size_t)(bb_ * PH + hh) * PS + s) * PDH + kc0;
        float o[8];
#pragma unroll
        for (int j = 0; j < 8; j++) o[j] = (acc[i][j] + bcol[j]) * scale;
        *(float4*)dst       = *(float4*)&o[0];
        *(float4*)(dst + 4) = *(float4*)&o[4];
    }
}

// ---------------------------------------------------------------------------
// Kernel 2: raw scores = Qh * Kh^T, written directly into aws[h][b][:, :]
// Per (b,h): M=N=2048, K=64. 128x128 tiles, 8x8 per thread.
// ---------------------------------------------------------------------------
__global__ __launch_bounds__(256) void scores_kernel(float* __restrict__ aw)
{
    __shared__ float As[16][132];
    __shared__ float Bs[16][132];

    const int zz = blockIdx.z;           // b*H + h
    const int b_ = zz >> 4, h_ = zz & 15;
    const float* Qh = g_Q + (size_t)zz * PS * PDH;
    const float* Kh = g_K + (size_t)zz * PS * PDH;
    float* awb = aw + (size_t)(h_ * PB + b_) * PS * PS;

    const int m0 = blockIdx.x * 128;     // query tile
    const int n0 = blockIdx.y * 128;     // key tile
    const int tid = threadIdx.x;
    const int tx = tid & 15, ty = tid >> 4;

    float acc[8][8];
#pragma unroll
    for (int i = 0; i < 8; i++)
#pragma unroll
        for (int j = 0; j < 8; j++) acc[i][j] = 0.f;

    for (int d0 = 0; d0 < PDH; d0 += 16) {
#pragma unroll
        for (int l = 0; l < 2; l++) {
            int f = tid + 256 * l;
            int m = f >> 2, c4 = (f & 3) * 4;
            float4 av = *(const float4*)(Qh + (size_t)(m0 + m) * PDH + d0 + c4);
            As[c4 + 0][m] = av.x; As[c4 + 1][m] = av.y;
            As[c4 + 2][m] = av.z; As[c4 + 3][m] = av.w;
            float4 kv = *(const float4*)(Kh + (size_t)(n0 + m) * PDH + d0 + c4);
            Bs[c4 + 0][m] = kv.x; Bs[c4 + 1][m] = kv.y;
            Bs[c4 + 2][m] = kv.z; Bs[c4 + 3][m] = kv.w;
        }
        __syncthreads();
#pragma unroll
        for (int kk = 0; kk < 16; kk++) {
            float a[8], bb[8];
            *(float4*)&a[0]  = *(const float4*)&As[kk][ty * 8];
            *(float4*)&a[4]  = *(const float4*)&As[kk][ty * 8 + 4];
            *(float4*)&bb[0] = *(const float4*)&Bs[kk][tx * 8];
            *(float4*)&bb[4] = *(const float4*)&Bs[kk][tx * 8 + 4];
#pragma unroll
            for (int i = 0; i < 8; i++)
#pragma unroll
                for (int j = 0; j < 8; j++) acc[i][j] += a[i] * bb[j];
        }
        __syncthreads();
    }

#pragma unroll
    for (int i = 0; i < 8; i++) {
        int qi = m0 + ty * 8 + i;
        float* dst = awb + (size_t)qi * PS + n0 + tx * 8;
        *(float4*)dst       = *(float4*)&acc[i][0];
        *(float4*)(dst + 4) = *(float4*)&acc[i][4];
    }
}

// ---------------------------------------------------------------------------
// Kernel 3: in-place row softmax over aws. One block per 2048-wide row,
// 8 elements per thread held in registers; two warp/block reductions.
// ---------------------------------------------------------------------------
__global__ __launch_bounds__(256) void softmax_kernel(float* __restrict__ aw)
{
    float* p = aw + (size_t)blockIdx.x * PS;
    const int t = threadIdx.x;
    const int lane = t & 31, warp = t >> 5;

    float x[8];
    *(float4*)&x[0] = ((const float4*)p)[t];
    *(float4*)&x[4] = ((const float4*)p)[t + 256];

    float m = x[0];
#pragma unroll
    for (int i = 1; i < 8; i++) m = fmaxf(m, x[i]);
#pragma unroll
    for (int o = 16; o > 0; o >>= 1) m = fmaxf(m, __shfl_xor_sync(0xffffffffu, m, o));

    __shared__ float red[8];
    if (lane == 0) red[warp] = m;
    __syncthreads();
    float mm = red[0];
#pragma unroll
    for (int i = 1; i < 8; i++) mm = fmaxf(mm, red[i]);

    float ssum = 0.f;
#pragma unroll
    for (int i = 0; i < 8; i++) { x[i] = __expf(x[i] - mm); ssum += x[i]; }
#pragma unroll
    for (int o = 16; o > 0; o >>= 1) ssum += __shfl_xor_sync(0xffffffffu, ssum, o);

    __syncthreads();                 // red[] reuse
    if (lane == 0) red[warp] = ssum;
    __syncthreads();
    float tot = 0.f;
#pragma unroll
    for (int i = 0; i < 8; i++) tot += red[i];
    float inv = 1.0f / tot;
#pragma unroll
    for (int i = 0; i < 8; i++) x[i] *= inv;

    ((float4*)p)[t]       = *(float4*)&x[0];
    ((float4*)p)[t + 256] = *(float4*)&x[4];
}

// ---------------------------------------------------------------------------
// Kernel 4: ctx = aw * V per (b,h): M=2048, N=64, K=2048. 128x64 tiles,
// 8x4 per thread. Output goes to head-concatenated [b][s][h*64+k].
// ---------------------------------------------------------------------------
__global__ __launch_bounds__(256) void ctx_kernel(const float* __restrict__ aw)
{
    __shared__ float As[16][132];   // transposed aw tile
    __shared__ float Bs[16][64];    // V tile, natural layout

    const int zz = blockIdx.z;
    const int b_ = zz >> 4, h_ = zz & 15;
    const float* awb = aw + (size_t)(h_ * PB + b_) * PS * PS;
    const float* Vh = g_V + (size_t)zz * PS * PDH;

    const int m0 = blockIdx.x * 128;
    const int tid = threadIdx.x;
    const int tx = tid & 15, ty = tid >> 4;

    float acc[8][4];
#pragma unroll
    for (int i = 0; i < 8; i++)
#pragma unroll
        for (int j = 0; j < 4; j++) acc[i][j] = 0.f;

    for (int kc = 0; kc < PS; kc += 16) {
#pragma unroll
        for (int l = 0; l < 2; l++) {
            int f = tid + 256 * l;
            int m = f >> 2, c4 = (f & 3) * 4;
            float4 av = *(const float4*)(awb + (size_t)(m0 + m) * PS + kc + c4);
            As[c4 + 0][m] = av.x; As[c4 + 1][m] = av.y;
            As[c4 + 2][m] = av.z; As[c4 + 3][m] = av.w;
        }
        {
            int kk = tid >> 4, c4 = (tid & 15) * 4;
            *(float4*)&Bs[kk][c4] =
                *(const float4*)(Vh + (size_t)(kc + kk) * PDH + c4);
        }
        __syncthreads();
#pragma unroll
        for (int kk = 0; kk < 16; kk++) {
            float a[8];
            *(float4*)&a[0] = *(const float4*)&As[kk][ty * 8];
            *(float4*)&a[4] = *(const float4*)&As[kk][ty * 8 + 4];
            float4 b4 = *(const float4*)&Bs[kk][tx * 4];
            float bb[4] = {b4.x, b4.y, b4.z, b4.w};
#pragma unroll
            for (int i = 0; i < 8; i++)
#pragma unroll
                for (int j = 0; j < 4; j++) acc[i][j] += a[i] * bb[j];
        }
        __syncthreads();
    }

#pragma unroll
    for (int i = 0; i < 8; i++) {
        int s = m0 + ty * 8 + i;
        *(float4*)(g_ctx + (size_t)(b_ * PS + s) * PD + h_ * PDH + tx * 4) =
            *(float4*)&acc[i][0];
    }
}

// ---------------------------------------------------------------------------
// Kernel 5: out = ctx @ Wo + bo. M=4096, N=1024, K=1024. 128x128 tiles.
// ---------------------------------------------------------------------------
__global__ __launch_bounds__(256) void out_proj_kernel(
    const float* __restrict__ Wo, const float* __restrict__ bo,
    float* __restrict__ out)
{
    __shared__ float As[16][132];
    __shared__ float Bs[16][128];

    const int m0 = blockIdx.x * 128;
    const int n0 = blockIdx.y * 128;
    const int tid = threadIdx.x;
    const int tx = tid & 15, ty = tid >> 4;

    float acc[8][8];
#pragma unroll
    for (int i = 0; i < 8; i++)
#pragma unroll
        for (int j = 0; j < 8; j++) acc[i][j] = 0.f;

    for (int d0 = 0; d0 < PD; d0 += 16) {
#pragma unroll
        for (int l = 0; l < 2; l++) {
            int f = tid + 256 * l;
            int m = f >> 2, c4 = (f & 3) * 4;
            float4 av = *(const float4*)(g_ctx + (size_t)(m0 + m) * PD + d0 + c4);
            As[c4 + 0][m] = av.x; As[c4 + 1][m] = av.y;
            As[c4 + 2][m] = av.z; As[c4 + 3][m] = av.w;
        }
#pragma unroll
        for (int l = 0; l < 2; l++) {
            int f = tid + 256 * l;
            int kk = f >> 5, c4 = (f & 31) * 4;
            *(float4*)&Bs[kk][c4] =
                *(const float4*)(Wo + (size_t)(d0 + kk) * PD + n0 + c4);
        }
        __syncthreads();
#pragma unroll
        for (int kk = 0; kk < 16; kk++) {
            float a[8], bb[8];
            *(float4*)&a[0]  = *(const float4*)&As[kk][ty * 8];
            *(float4*)&a[4]  = *(const float4*)&As[kk][ty * 8 + 4];
            *(float4*)&bb[0] = *(const float4*)&Bs[kk][tx * 8];
            *(float4*)&bb[4] = *(const float4*)&Bs[kk][tx * 8 + 4];
#pragma unroll
            for (int i = 0; i < 8; i++)
#pragma unroll
                for (int j = 0; j < 8; j++) acc[i][j] += a[i] * bb[j];
        }
        __syncthreads();
    }

    float bcol[8];
#pragma unroll
    for (int j = 0; j < 8; j++) bcol[j] = bo[n0 + tx * 8 + j];

#pragma unroll
    for (int i = 0; i < 8; i++) {
        int r = m0 + ty * 8 + i;
        float* dst = out + (size_t)r * PD + n0 + tx * 8;
        float o[8];
#pragma unroll
        for (int j = 0; j < 8; j++) o[j] = acc[i][j] + bcol[j];
        *(float4*)dst       = *(float4*)&o[0];
        *(float4*)(dst + 4) = *(float4*)&o[4];
    }
}

// ---------------------------------------------------------------------------
extern "C" void kernel_launch(void* const* d_in, const int* in_sizes, int n_in,
                              void* d_out, int out_size)
{
    (void)in_sizes; (void)n_in; (void)out_size;
    const float* q  = (const float*)d_in[0];
    const float* k  = (const float*)d_in[1];
    const float* v  = (const float*)d_in[2];
    const float* Wq = (const float*)d_in[3];
    const float* Wk = (const float*)d_in[4];
    const float* Wv = (const float*)d_in[5];
    const float* bq = (const float*)d_in[6];
    const float* bk = (const float*)d_in[7];
    const float* bv = (const float*)d_in[8];
    const float* Wo = (const float*)d_in[9];
    const float* bo = (const float*)d_in[10];

    float* out = (float*)d_out;
    float* aw  = out + OUT_ELEMS;    // aws [H][B][S][S] follows out [B][S][D]

    qkv_proj_kernel<<<dim3(PBS / 128, PD / 128, 3), 256>>>(
        q, k, v, Wq, Wk, Wv, bq, bk, bv);
    scores_kernel<<<dim3(PS / 128, PS / 128, PB * PH), 256>>>(aw);
    softmax_kernel<<<PB * PH * PS, 256>>>(aw);
    ctx_kernel<<<dim3(PS / 128, 1, PB * PH), 256>>>(aw);
    out_proj_kernel<<<dim3(PBS / 128, PD / 128), 256>>>(Wo, bo, out);
}

// round 9
// speedup vs baseline: 1.0018x; 1.0009x over previous
#include <cuda_runtime.h>

// Problem constants
#define PB 2
#define PS 2048
#define PD 1024
#define PH 16
#define PDH 64
#define PBS (PB * PS)                        // 4096 rows
#define OUT_ELEMS ((long long)PB * PS * PD)  // 4194304

// Scratch (device globals; no allocation allowed)
__device__ float g_Q[(size_t)PB * PH * PS * PDH];   // [b][h][s][k]
__device__ float g_K[(size_t)PB * PH * PS * PDH];
__device__ float g_V[(size_t)PB * PH * PS * PDH];
__device__ float g_ctx[(size_t)PB * PS * PD];       // [b][s][h*64+k]

// ---------------------------------------------------------------------------
// Kernel 1: fused Q/K/V per-head projections.
// C[128 x 128] = A[128 x 1024] * W[1024 x 128] (+bias, Q scaled by 1/8)
// blockIdx.x: M tile (128 rows of B*S), blockIdx.y: 2 heads, blockIdx.z: q/k/v
// ---------------------------------------------------------------------------
__global__ __launch_bounds__(256) void qkv_proj_kernel(
    const float* __restrict__ q, const float* __restrict__ k,
    const float* __restrict__ v, const float* __restrict__ Wq,
    const float* __restrict__ Wk, const float* __restrict__ Wv,
    const float* __restrict__ bq, const float* __restrict__ bk,
    const float* __restrict__ bv)
{
    __shared__ float As[16][132];   // transposed: As[kk][m]
    __shared__ float Bs[16][128];   // Bs[kk][j]

    const int zz = blockIdx.z;
    const float* A    = (zz == 0) ? q  : (zz == 1) ? k  : v;
    const float* W    = (zz == 0) ? Wq : (zz == 1) ? Wk : Wv;
    const float* bias = (zz == 0) ? bq : (zz == 1) ? bk : bv;
    float* outp       = (zz == 0) ? g_Q : (zz == 1) ? g_K : g_V;
    const float scale = (zz == 0) ? 0.125f : 1.0f;   // 1/sqrt(DH) folded into Q

    const int m0 = blockIdx.x * 128;
    const int h0 = blockIdx.y * 2;          // two heads per N-tile of 128
    const int tid = threadIdx.x;
    const int tx = tid & 15;
    const int ty = tid >> 4;

    float acc[8][8];
#pragma unroll
    for (int i = 0; i < 8; i++)
#pragma unroll
        for (int j = 0; j < 8; j++) acc[i][j] = 0.f;

    for (int d0 = 0; d0 < PD; d0 += 16) {
        // A tile 128x16, transposed into smem
#pragma unroll
        for (int l = 0; l < 2; l++) {
            int f = tid + 256 * l;
            int m = f >> 2, c4 = (f & 3) * 4;
            float4 av = *(const float4*)(A + (size_t)(m0 + m) * PD + d0 + c4);
            As[c4 + 0][m] = av.x; As[c4 + 1][m] = av.y;
            As[c4 + 2][m] = av.z; As[c4 + 3][m] = av.w;
        }
        // W tile 16x128 (two heads, each contiguous 64-wide)
#pragma unroll
        for (int l = 0; l < 2; l++) {
            int f = tid + 256 * l;
            int kk = f >> 5, c4 = (f & 31) * 4;
            int hh = h0 + (c4 >> 6);
            int kc = c4 & 63;
            *(float4*)&Bs[kk][c4] =
                *(const float4*)(W + ((size_t)hh * PD + (d0 + kk)) * PDH + kc);
        }
        __syncthreads();
#pragma unroll
        for (int kk = 0; kk < 16; kk++) {
            float a[8], bb[8];
            *(float4*)&a[0]  = *(const float4*)&As[kk][ty * 8];
            *(float4*)&a[4]  = *(const float4*)&As[kk][ty * 8 + 4];
            *(float4*)&bb[0] = *(const float4*)&Bs[kk][tx * 8];
            *(float4*)&bb[4] = *(const float4*)&Bs[kk][tx * 8 + 4];
#pragma unroll
            for (int i = 0; i < 8; i++)
#pragma unroll
                for (int j = 0; j < 8; j++) acc[i][j] += a[i] * bb[j];
        }
        __syncthreads();
    }

    // epilogue: bias + scale, store to [b][h][s][k] layout
    const int jbase = tx * 8;              // 8 cols, never straddles a head
    const int hh = h0 + (jbase >> 6);
    const int kc0 = jbase & 63;
    float bcol[8];
#pragma unroll
    for (int j = 0; j < 8; j++) bcol[j] = bias[hh * PDH + kc0 + j];

#pragma unroll
    for (int i = 0; i < 8; i++) {
        int r = m0 + ty * 8 + i;
        int bb_ = r >> 11;                 // / S
        int s = r & (PS - 1);
        float* dst = outp + ((size_t)(bb_ * PH + hh) * PS + s) * PDH + kc0;
        float o[8];
#pragma unroll
        for (int j = 0; j < 8; j++) o[j] = (acc[i][j] + bcol[j]) * scale;
        *(float4*)dst       = *(float4*)&o[0];
        *(float4*)(dst + 4) = *(float4*)&o[4];
    }
}

// ---------------------------------------------------------------------------
// Kernel 2: raw scores = Qh * Kh^T, written directly into aws[h][b][:, :]
// Per (b,h): M=N=2048, K=64. 128x128 tiles, 8x8 per thread.
// ---------------------------------------------------------------------------
__global__ __launch_bounds__(256) void scores_kernel(float* __restrict__ aw)
{
    __shared__ float As[16][132];
    __shared__ float Bs[16][132];

    const int zz = blockIdx.z;           // b*H + h
    const int b_ = zz >> 4, h_ = zz & 15;
    const float* Qh = g_Q + (size_t)zz * PS * PDH;
    const float* Kh = g_K + (size_t)zz * PS * PDH;
    float* awb = aw + (size_t)(h_ * PB + b_) * PS * PS;

    const int m0 = blockIdx.x * 128;     // query tile
    const int n0 = blockIdx.y * 128;     // key tile
    const int tid = threadIdx.x;
    const int tx = tid & 15, ty = tid >> 4;

    float acc[8][8];
#pragma unroll
    for (int i = 0; i < 8; i++)
#pragma unroll
        for (int j = 0; j < 8; j++) acc[i][j] = 0.f;

    for (int d0 = 0; d0 < PDH; d0 += 16) {
#pragma unroll
        for (int l = 0; l < 2; l++) {
            int f = tid + 256 * l;
            int m = f >> 2, c4 = (f & 3) * 4;
            float4 av = *(const float4*)(Qh + (size_t)(m0 + m) * PDH + d0 + c4);
            As[c4 + 0][m] = av.x; As[c4 + 1][m] = av.y;
            As[c4 + 2][m] = av.z; As[c4 + 3][m] = av.w;
            float4 kv = *(const float4*)(Kh + (size_t)(n0 + m) * PDH + d0 + c4);
            Bs[c4 + 0][m] = kv.x; Bs[c4 + 1][m] = kv.y;
            Bs[c4 + 2][m] = kv.z; Bs[c4 + 3][m] = kv.w;
        }
        __syncthreads();
#pragma unroll
        for (int kk = 0; kk < 16; kk++) {
            float a[8], bb[8];
            *(float4*)&a[0]  = *(const float4*)&As[kk][ty * 8];
            *(float4*)&a[4]  = *(const float4*)&As[kk][ty * 8 + 4];
            *(float4*)&bb[0] = *(const float4*)&Bs[kk][tx * 8];
            *(float4*)&bb[4] = *(const float4*)&Bs[kk][tx * 8 + 4];
#pragma unroll
            for (int i = 0; i < 8; i++)
#pragma unroll
                for (int j = 0; j < 8; j++) acc[i][j] += a[i] * bb[j];
        }
        __syncthreads();
    }

#pragma unroll
    for (int i = 0; i < 8; i++) {
        int qi = m0 + ty * 8 + i;
        float* dst = awb + (size_t)qi * PS + n0 + tx * 8;
        *(float4*)dst       = *(float4*)&acc[i][0];
        *(float4*)(dst + 4) = *(float4*)&acc[i][4];
    }
}

// ---------------------------------------------------------------------------
// Kernel 3: in-place row softmax over aws. One block per 2048-wide row,
// 8 elements per thread held in registers; two warp/block reductions.
// ---------------------------------------------------------------------------
__global__ __launch_bounds__(256) void softmax_kernel(float* __restrict__ aw)
{
    float* p = aw + (size_t)blockIdx.x * PS;
    const int t = threadIdx.x;
    const int lane = t & 31, warp = t >> 5;

    float x[8];
    *(float4*)&x[0] = ((const float4*)p)[t];
    *(float4*)&x[4] = ((const float4*)p)[t + 256];

    float m = x[0];
#pragma unroll
    for (int i = 1; i < 8; i++) m = fmaxf(m, x[i]);
#pragma unroll
    for (int o = 16; o > 0; o >>= 1) m = fmaxf(m, __shfl_xor_sync(0xffffffffu, m, o));

    __shared__ float red[8];
    if (lane == 0) red[warp] = m;
    __syncthreads();
    float mm = red[0];
#pragma unroll
    for (int i = 1; i < 8; i++) mm = fmaxf(mm, red[i]);

    float ssum = 0.f;
#pragma unroll
    for (int i = 0; i < 8; i++) { x[i] = __expf(x[i] - mm); ssum += x[i]; }
#pragma unroll
    for (int o = 16; o > 0; o >>= 1) ssum += __shfl_xor_sync(0xffffffffu, ssum, o);

    __syncthreads();                 // red[] reuse
    if (lane == 0) red[warp] = ssum;
    __syncthreads();
    float tot = 0.f;
#pragma unroll
    for (int i = 0; i < 8; i++) tot += red[i];
    float inv = 1.0f / tot;
#pragma unroll
    for (int i = 0; i < 8; i++) x[i] *= inv;

    ((float4*)p)[t]       = *(float4*)&x[0];
    ((float4*)p)[t + 256] = *(float4*)&x[4];
}

// ---------------------------------------------------------------------------
// Kernel 4: ctx = aw * V per (b,h): M=2048, N=64, K=2048. 128x64 tiles,
// 8x4 per thread. Output goes to head-concatenated [b][s][h*64+k].
// ---------------------------------------------------------------------------
__global__ __launch_bounds__(256) void ctx_kernel(const float* __restrict__ aw)
{
    __shared__ float As[16][132];   // transposed aw tile
    __shared__ float Bs[16][64];    // V tile, natural layout

    const int zz = blockIdx.z;
    const int b_ = zz >> 4, h_ = zz & 15;
    const float* awb = aw + (size_t)(h_ * PB + b_) * PS * PS;
    const float* Vh = g_V + (size_t)zz * PS * PDH;

    const int m0 = blockIdx.x * 128;
    const int tid = threadIdx.x;
    const int tx = tid & 15, ty = tid >> 4;

    float acc[8][4];
#pragma unroll
    for (int i = 0; i < 8; i++)
#pragma unroll
        for (int j = 0; j < 4; j++) acc[i][j] = 0.f;

    for (int kc = 0; kc < PS; kc += 16) {
#pragma unroll
        for (int l = 0; l < 2; l++) {
            int f = tid + 256 * l;
            int m = f >> 2, c4 = (f & 3) * 4;
            float4 av = *(const float4*)(awb + (size_t)(m0 + m) * PS + kc + c4);
            As[c4 + 0][m] = av.x; As[c4 + 1][m] = av.y;
            As[c4 + 2][m] = av.z; As[c4 + 3][m] = av.w;
        }
        {
            int kk = tid >> 4, c4 = (tid & 15) * 4;
            *(float4*)&Bs[kk][c4] =
                *(const float4*)(Vh + (size_t)(kc + kk) * PDH + c4);
        }
        __syncthreads();
#pragma unroll
        for (int kk = 0; kk < 16; kk++) {
            float a[8];
            *(float4*)&a[0] = *(const float4*)&As[kk][ty * 8];
            *(float4*)&a[4] = *(const float4*)&As[kk][ty * 8 + 4];
            float4 b4 = *(const float4*)&Bs[kk][tx * 4];
            float bb[4] = {b4.x, b4.y, b4.z, b4.w};
#pragma unroll
            for (int i = 0; i < 8; i++)
#pragma unroll
                for (int j = 0; j < 4; j++) acc[i][j] += a[i] * bb[j];
        }
        __syncthreads();
    }

#pragma unroll
    for (int i = 0; i < 8; i++) {
        int s = m0 + ty * 8 + i;
        *(float4*)(g_ctx + (size_t)(b_ * PS + s) * PD + h_ * PDH + tx * 4) =
            *(float4*)&acc[i][0];
    }
}

// ---------------------------------------------------------------------------
// Kernel 5: out = ctx @ Wo + bo. M=4096, N=1024, K=1024. 128x128 tiles.
// ---------------------------------------------------------------------------
__global__ __launch_bounds__(256) void out_proj_kernel(
    const float* __restrict__ Wo, const float* __restrict__ bo,
    float* __restrict__ out)
{
    __shared__ float As[16][132];
    __shared__ float Bs[16][128];

    const int m0 = blockIdx.x * 128;
    const int n0 = blockIdx.y * 128;
    const int tid = threadIdx.x;
    const int tx = tid & 15, ty = tid >> 4;

    float acc[8][8];
#pragma unroll
    for (int i = 0; i < 8; i++)
#pragma unroll
        for (int j = 0; j < 8; j++) acc[i][j] = 0.f;

    for (int d0 = 0; d0 < PD; d0 += 16) {
#pragma unroll
        for (int l = 0; l < 2; l++) {
            int f = tid + 256 * l;
            int m = f >> 2, c4 = (f & 3) * 4;
            float4 av = *(const float4*)(g_ctx + (size_t)(m0 + m) * PD + d0 + c4);
            As[c4 + 0][m] = av.x; As[c4 + 1][m] = av.y;
            As[c4 + 2][m] = av.z; As[c4 + 3][m] = av.w;
        }
#pragma unroll
        for (int l = 0; l < 2; l++) {
            int f = tid + 256 * l;
            int kk = f >> 5, c4 = (f & 31) * 4;
            *(float4*)&Bs[kk][c4] =
                *(const float4*)(Wo + (size_t)(d0 + kk) * PD + n0 + c4);
        }
        __syncthreads();
#pragma unroll
        for (int kk = 0; kk < 16; kk++) {
            float a[8], bb[8];
            *(float4*)&a[0]  = *(const float4*)&As[kk][ty * 8];
            *(float4*)&a[4]  = *(const float4*)&As[kk][ty * 8 + 4];
            *(float4*)&bb[0] = *(const float4*)&Bs[kk][tx * 8];
            *(float4*)&bb[4] = *(const float4*)&Bs[kk][tx * 8 + 4];
#pragma unroll
            for (int i = 0; i < 8; i++)
#pragma unroll
                for (int j = 0; j < 8; j++) acc[i][j] += a[i] * bb[j];
        }
        __syncthreads();
    }

    float bcol[8];
#pragma unroll
    for (int j = 0; j < 8; j++) bcol[j] = bo[n0 + tx * 8 + j];

#pragma unroll
    for (int i = 0; i < 8; i++) {
        int r = m0 + ty * 8 + i;
        float* dst = out + (size_t)r * PD + n0 + tx * 8;
        float o[8];
#pragma unroll
        for (int j = 0; j < 8; j++) o[j] = acc[i][j] + bcol[j];
        *(float4*)dst       = *(float4*)&o[0];
        *(float4*)(dst + 4) = *(float4*)&o[4];
    }
}

// ---------------------------------------------------------------------------
extern "C" void kernel_launch(void* const* d_in, const int* in_sizes, int n_in,
                              void* d_out, int out_size)
{
    (void)in_sizes; (void)n_in; (void)out_size;
    const float* q  = (const float*)d_in[0];
    const float* k  = (const float*)d_in[1];
    const float* v  = (const float*)d_in[2];
    const float* Wq = (const float*)d_in[3];
    const float* Wk = (const float*)d_in[4];
    const float* Wv = (const float*)d_in[5];
    const float* bq = (const float*)d_in[6];
    const float* bk = (const float*)d_in[7];
    const float* bv = (const float*)d_in[8];
    const float* Wo = (const float*)d_in[9];
    const float* bo = (const float*)d_in[10];

    float* out = (float*)d_out;
    float* aw  = out + OUT_ELEMS;    // aws [H][B][S][S] follows out [B][S][D]

    qkv_proj_kernel<<<dim3(PBS / 128, PD / 128, 3), 256>>>(
        q, k, v, Wq, Wk, Wv, bq, bk, bv);
    scores_kernel<<<dim3(PS / 128, PS / 128, PB * PH), 256>>>(aw);
    softmax_kernel<<<PB * PH * PS, 256>>>(aw);
    ctx_kernel<<<dim3(PS / 128, 1, PB * PH), 256>>>(aw);
    out_proj_kernel<<<dim3(PBS / 128, PD / 128), 256>>>(Wo, bo, out);
}

// round 10
// speedup vs baseline: 1.0023x; 1.0005x over previous
#include <cuda_runtime.h>

// Problem constants
#define PB 2
#define PS 2048
#define PD 1024
#define PH 16
#define PDH 64
#define PBS (PB * PS)                        // 4096 rows
#define OUT_ELEMS ((long long)PB * PS * PD)  // 4194304

// Scratch (device globals; no allocation allowed)
__device__ float g_Q[(size_t)PB * PH * PS * PDH];   // [b][h][s][k]
__device__ float g_K[(size_t)PB * PH * PS * PDH];
__device__ float g_V[(size_t)PB * PH * PS * PDH];
__device__ float g_ctx[(size_t)PB * PS * PD];       // [b][s][h*64+k]

// ---------------------------------------------------------------------------
// Kernel 1: fused Q/K/V per-head projections.
// C[128 x 128] = A[128 x 1024] * W[1024 x 128] (+bias, Q scaled by 1/8)
// blockIdx.x: M tile (128 rows of B*S), blockIdx.y: 2 heads, blockIdx.z: q/k/v
// ---------------------------------------------------------------------------
__global__ __launch_bounds__(256) void qkv_proj_kernel(
    const float* __restrict__ q, const float* __restrict__ k,
    const float* __restrict__ v, const float* __restrict__ Wq,
    const float* __restrict__ Wk, const float* __restrict__ Wv,
    const float* __restrict__ bq, const float* __restrict__ bk,
    const float* __restrict__ bv)
{
    __shared__ float As[16][132];   // transposed: As[kk][m]
    __shared__ float Bs[16][128];   // Bs[kk][j]

    const int zz = blockIdx.z;
    const float* A    = (zz == 0) ? q  : (zz == 1) ? k  : v;
    const float* W    = (zz == 0) ? Wq : (zz == 1) ? Wk : Wv;
    const float* bias = (zz == 0) ? bq : (zz == 1) ? bk : bv;
    float* outp       = (zz == 0) ? g_Q : (zz == 1) ? g_K : g_V;
    const float scale = (zz == 0) ? 0.125f : 1.0f;   // 1/sqrt(DH) folded into Q

    const int m0 = blockIdx.x * 128;
    const int h0 = blockIdx.y * 2;          // two heads per N-tile of 128
    const int tid = threadIdx.x;
    const int tx = tid & 15;
    const int ty = tid >> 4;

    float acc[8][8];
#pragma unroll
    for (int i = 0; i < 8; i++)
#pragma unroll
        for (int j = 0; j < 8; j++) acc[i][j] = 0.f;

    for (int d0 = 0; d0 < PD; d0 += 16) {
        // A tile 128x16, transposed into smem
#pragma unroll
        for (int l = 0; l < 2; l++) {
            int f = tid + 256 * l;
            int m = f >> 2, c4 = (f & 3) * 4;
            float4 av = *(const float4*)(A + (size_t)(m0 + m) * PD + d0 + c4);
            As[c4 + 0][m] = av.x; As[c4 + 1][m] = av.y;
            As[c4 + 2][m] = av.z; As[c4 + 3][m] = av.w;
        }
        // W tile 16x128 (two heads, each contiguous 64-wide)
#pragma unroll
        for (int l = 0; l < 2; l++) {
            int f = tid + 256 * l;
            int kk = f >> 5, c4 = (f & 31) * 4;
            int hh = h0 + (c4 >> 6);
            int kc = c4 & 63;
            *(float4*)&Bs[kk][c4] =
                *(const float4*)(W + ((size_t)hh * PD + (d0 + kk)) * PDH + kc);
        }
        __syncthreads();
#pragma unroll
        for (int kk = 0; kk < 16; kk++) {
            float a[8], bb[8];
            *(float4*)&a[0]  = *(const float4*)&As[kk][ty * 8];
            *(float4*)&a[4]  = *(const float4*)&As[kk][ty * 8 + 4];
            *(float4*)&bb[0] = *(const float4*)&Bs[kk][tx * 8];
            *(float4*)&bb[4] = *(const float4*)&Bs[kk][tx * 8 + 4];
#pragma unroll
            for (int i = 0; i < 8; i++)
#pragma unroll
                for (int j = 0; j < 8; j++) acc[i][j] += a[i] * bb[j];
        }
        __syncthreads();
    }

    // epilogue: bias + scale, store to [b][h][s][k] layout
    const int jbase = tx * 8;              // 8 cols, never straddles a head
    const int hh = h0 + (jbase >> 6);
    const int kc0 = jbase & 63;
    float bcol[8];
#pragma unroll
    for (int j = 0; j < 8; j++) bcol[j] = bias[hh * PDH + kc0 + j];

#pragma unroll
    for (int i = 0; i < 8; i++) {
        int r = m0 + ty * 8 + i;
        int bb_ = r >> 11;                 // / S
        int s = r & (PS - 1);
        float* dst = outp + ((size_t)(bb_ * PH + hh) * PS + s) * PDH + kc0;
        float o[8];
#pragma unroll
        for (int j = 0; j < 8; j++) o[j] = (acc[i][j] + bcol[j]) * scale;
        *(float4*)dst       = *(float4*)&o[0];
        *(float4*)(dst + 4) = *(float4*)&o[4];
    }
}

// ---------------------------------------------------------------------------
// Kernel 2: raw scores = Qh * Kh^T, written directly into aws[h][b][:, :]
// Per (b,h): M=N=2048, K=64. 128x128 tiles, 8x8 per thread.
// ---------------------------------------------------------------------------
__global__ __launch_bounds__(256) void scores_kernel(float* __restrict__ aw)
{
    __shared__ float As[16][132];
    __shared__ float Bs[16][132];

    const int zz = blockIdx.z;           // b*H + h
    const int b_ = zz >> 4, h_ = zz & 15;
    const float* Qh = g_Q + (size_t)zz * PS * PDH;
    const float* Kh = g_K + (size_t)zz * PS * PDH;
    float* awb = aw + (size_t)(h_ * PB + b_) * PS * PS;

    const int m0 = blockIdx.x * 128;     // query tile
    const int n0 = blockIdx.y * 128;     // key tile
    const int tid = threadIdx.x;
    const int tx = tid & 15, ty = tid >> 4;

    float acc[8][8];
#pragma unroll
    for (int i = 0; i < 8; i++)
#pragma unroll
        for (int j = 0; j < 8; j++) acc[i][j] = 0.f;

    for (int d0 = 0; d0 < PDH; d0 += 16) {
#pragma unroll
        for (int l = 0; l < 2; l++) {
            int f = tid + 256 * l;
            int m = f >> 2, c4 = (f & 3) * 4;
            float4 av = *(const float4*)(Qh + (size_t)(m0 + m) * PDH + d0 + c4);
            As[c4 + 0][m] = av.x; As[c4 + 1][m] = av.y;
            As[c4 + 2][m] = av.z; As[c4 + 3][m] = av.w;
            float4 kv = *(const float4*)(Kh + (size_t)(n0 + m) * PDH + d0 + c4);
            Bs[c4 + 0][m] = kv.x; Bs[c4 + 1][m] = kv.y;
            Bs[c4 + 2][m] = kv.z; Bs[c4 + 3][m] = kv.w;
        }
        __syncthreads();
#pragma unroll
        for (int kk = 0; kk < 16; kk++) {
            float a[8], bb[8];
            *(float4*)&a[0]  = *(const float4*)&As[kk][ty * 8];
            *(float4*)&a[4]  = *(const float4*)&As[kk][ty * 8 + 4];
            *(float4*)&bb[0] = *(const float4*)&Bs[kk][tx * 8];
            *(float4*)&bb[4] = *(const float4*)&Bs[kk][tx * 8 + 4];
#pragma unroll
            for (int i = 0; i < 8; i++)
#pragma unroll
                for (int j = 0; j < 8; j++) acc[i][j] += a[i] * bb[j];
        }
        __syncthreads();
    }

#pragma unroll
    for (int i = 0; i < 8; i++) {
        int qi = m0 + ty * 8 + i;
        float* dst = awb + (size_t)qi * PS + n0 + tx * 8;
        *(float4*)dst       = *(float4*)&acc[i][0];
        *(float4*)(dst + 4) = *(float4*)&acc[i][4];
    }
}

// ---------------------------------------------------------------------------
// Kernel 3: in-place row softmax over aws. One block per 2048-wide row,
// 8 elements per thread held in registers; two warp/block reductions.
// ---------------------------------------------------------------------------
__global__ __launch_bounds__(256) void softmax_kernel(float* __restrict__ aw)
{
    float* p = aw + (size_t)blockIdx.x * PS;
    const int t = threadIdx.x;
    const int lane = t & 31, warp = t >> 5;

    float x[8];
    *(float4*)&x[0] = ((const float4*)p)[t];
    *(float4*)&x[4] = ((const float4*)p)[t + 256];

    float m = x[0];
#pragma unroll
    for (int i = 1; i < 8; i++) m = fmaxf(m, x[i]);
#pragma unroll
    for (int o = 16; o > 0; o >>= 1) m = fmaxf(m, __shfl_xor_sync(0xffffffffu, m, o));

    __shared__ float red[8];
    if (lane == 0) red[warp] = m;
    __syncthreads();
    float mm = red[0];
#pragma unroll
    for (int i = 1; i < 8; i++) mm = fmaxf(mm, red[i]);

    float ssum = 0.f;
#pragma unroll
    for (int i = 0; i < 8; i++) { x[i] = __expf(x[i] - mm); ssum += x[i]; }
#pragma unroll
    for (int o = 16; o > 0; o >>= 1) ssum += __shfl_xor_sync(0xffffffffu, ssum, o);

    __syncthreads();                 // red[] reuse
    if (lane == 0) red[warp] = ssum;
    __syncthreads();
    float tot = 0.f;
#pragma unroll
    for (int i = 0; i < 8; i++) tot += red[i];
    float inv = 1.0f / tot;
#pragma unroll
    for (int i = 0; i < 8; i++) x[i] *= inv;

    ((float4*)p)[t]       = *(float4*)&x[0];
    ((float4*)p)[t + 256] = *(float4*)&x[4];
}

// ---------------------------------------------------------------------------
// Kernel 4: ctx = aw * V per (b,h): M=2048, N=64, K=2048. 128x64 tiles,
// 8x4 per thread. Output goes to head-concatenated [b][s][h*64+k].
// ---------------------------------------------------------------------------
__global__ __launch_bounds__(256) void ctx_kernel(const float* __restrict__ aw)
{
    __shared__ float As[16][132];   // transposed aw tile
    __shared__ float Bs[16][64];    // V tile, natural layout

    const int zz = blockIdx.z;
    const int b_ = zz >> 4, h_ = zz & 15;
    const float* awb = aw + (size_t)(h_ * PB + b_) * PS * PS;
    const float* Vh = g_V + (size_t)zz * PS * PDH;

    const int m0 = blockIdx.x * 128;
    const int tid = threadIdx.x;
    const int tx = tid & 15, ty = tid >> 4;

    float acc[8][4];
#pragma unroll
    for (int i = 0; i < 8; i++)
#pragma unroll
        for (int j = 0; j < 4; j++) acc[i][j] = 0.f;

    for (int kc = 0; kc < PS; kc += 16) {
#pragma unroll
        for (int l = 0; l < 2; l++) {
            int f = tid + 256 * l;
            int m = f >> 2, c4 = (f & 3) * 4;
            float4 av = *(const float4*)(awb + (size_t)(m0 + m) * PS + kc + c4);
            As[c4 + 0][m] = av.x; As[c4 + 1][m] = av.y;
            As[c4 + 2][m] = av.z; As[c4 + 3][m] = av.w;
        }
        {
            int kk = tid >> 4, c4 = (tid & 15) * 4;
            *(float4*)&Bs[kk][c4] =
                *(const float4*)(Vh + (size_t)(kc + kk) * PDH + c4);
        }
        __syncthreads();
#pragma unroll
        for (int kk = 0; kk < 16; kk++) {
            float a[8];
            *(float4*)&a[0] = *(const float4*)&As[kk][ty * 8];
            *(float4*)&a[4] = *(const float4*)&As[kk][ty * 8 + 4];
            float4 b4 = *(const float4*)&Bs[kk][tx * 4];
            float bb[4] = {b4.x, b4.y, b4.z, b4.w};
#pragma unroll
            for (int i = 0; i < 8; i++)
#pragma unroll
                for (int j = 0; j < 4; j++) acc[i][j] += a[i] * bb[j];
        }
        __syncthreads();
    }

#pragma unroll
    for (int i = 0; i < 8; i++) {
        int s = m0 + ty * 8 + i;
        *(float4*)(g_ctx + (size_t)(b_ * PS + s) * PD + h_ * PDH + tx * 4) =
            *(float4*)&acc[i][0];
    }
}

// ---------------------------------------------------------------------------
// Kernel 5: out = ctx @ Wo + bo. M=4096, N=1024, K=1024. 128x128 tiles.
// ---------------------------------------------------------------------------
__global__ __launch_bounds__(256) void out_proj_kernel(
    const float* __restrict__ Wo, const float* __restrict__ bo,
    float* __restrict__ out)
{
    __shared__ float As[16][132];
    __shared__ float Bs[16][128];

    const int m0 = blockIdx.x * 128;
    const int n0 = blockIdx.y * 128;
    const int tid = threadIdx.x;
    const int tx = tid & 15, ty = tid >> 4;

    float acc[8][8];
#pragma unroll
    for (int i = 0; i < 8; i++)
#pragma unroll
        for (int j = 0; j < 8; j++) acc[i][j] = 0.f;

    for (int d0 = 0; d0 < PD; d0 += 16) {
#pragma unroll
        for (int l = 0; l < 2; l++) {
            int f = tid + 256 * l;
            int m = f >> 2, c4 = (f & 3) * 4;
            float4 av = *(const float4*)(g_ctx + (size_t)(m0 + m) * PD + d0 + c4);
            As[c4 + 0][m] = av.x; As[c4 + 1][m] = av.y;
            As[c4 + 2][m] = av.z; As[c4 + 3][m] = av.w;
        }
#pragma unroll
        for (int l = 0; l < 2; l++) {
            int f = tid + 256 * l;
            int kk = f >> 5, c4 = (f & 31) * 4;
            *(float4*)&Bs[kk][c4] =
                *(const float4*)(Wo + (size_t)(d0 + kk) * PD + n0 + c4);
        }
        __syncthreads();
#pragma unroll
        for (int kk = 0; kk < 16; kk++) {
            float a[8], bb[8];
            *(float4*)&a[0]  = *(const float4*)&As[kk][ty * 8];
            *(float4*)&a[4]  = *(const float4*)&As[kk][ty * 8 + 4];
            *(float4*)&bb[0] = *(const float4*)&Bs[kk][tx * 8];
            *(float4*)&bb[4] = *(const float4*)&Bs[kk][tx * 8 + 4];
#pragma unroll
            for (int i = 0; i < 8; i++)
#pragma unroll
                for (int j = 0; j < 8; j++) acc[i][j] += a[i] * bb[j];
        }
        __syncthreads();
    }

    float bcol[8];
#pragma unroll
    for (int j = 0; j < 8; j++) bcol[j] = bo[n0 + tx * 8 + j];

#pragma unroll
    for (int i = 0; i < 8; i++) {
        int r = m0 + ty * 8 + i;
        float* dst = out + (size_t)r * PD + n0 + tx * 8;
        float o[8];
#pragma unroll
        for (int j = 0; j < 8; j++) o[j] = acc[i][j] + bcol[j];
        *(float4*)dst       = *(float4*)&o[0];
        *(float4*)(dst + 4) = *(float4*)&o[4];
    }
}

// ---------------------------------------------------------------------------
extern "C" void kernel_launch(void* const* d_in, const int* in_sizes, int n_in,
                              void* d_out, int out_size)
{
    (void)in_sizes; (void)n_in; (void)out_size;
    const float* q  = (const float*)d_in[0];
    const float* k  = (const float*)d_in[1];
    const float* v  = (const float*)d_in[2];
    const float* Wq = (const float*)d_in[3];
    const float* Wk = (const float*)d_in[4];
    const float* Wv = (const float*)d_in[5];
    const float* bq = (const float*)d_in[6];
    const float* bk = (const float*)d_in[7];
    const float* bv = (const float*)d_in[8];
    const float* Wo = (const float*)d_in[9];
    const float* bo = (const float*)d_in[10];

    float* out = (float*)d_out;
    float* aw  = out + OUT_ELEMS;    // aws [H][B][S][S] follows out [B][S][D]

    qkv_proj_kernel<<<dim3(PBS / 128, PD / 128, 3), 256>>>(
        q, k, v, Wq, Wk, Wv, bq, bk, bv);
    scores_kernel<<<dim3(PS / 128, PS / 128, PB * PH), 256>>>(aw);
    softmax_kernel<<<PB * PH * PS, 256>>>(aw);
    ctx_kernel<<<dim3(PS / 128, 1, PB * PH), 256>>>(aw);
    out_proj_kernel<<<dim3(PBS / 128, PD / 128), 256>>>(Wo, bo, out);
}